// round 3
// baseline (speedup 1.0000x reference)
#include <cuda_runtime.h>

#define NB 16
#define DD 128
#define NN 16
#define EE 120
#define JS 4          // j-slices of the 128-wide middle dimension
#define JW 32         // j per slice

// Scratch (allocation-free rule: __device__ globals)
__device__ float g_Pp[2 * JS * NB * 256];  // partial P[mat][js][b][u*16+v]
__device__ float g_Mp[NB * 256];           // U_src^T U_tgt
__device__ float g_mb[NB * EE];            // combined edge mask

// strict-upper-triangle edge index (numpy triu_indices(16, k=1) row-major)
__device__ __forceinline__ int eidx(int i, int j) {
    return i * 15 - ((i * (i - 1)) >> 1) + (j - i - 1);
}

// kA: partial P[mat][b] = F_src[b]^T * relu(lam+lam^T)[:, j0:j0+32] * F_tgt[b][j0:j0+32]
// grid (JS, NB, 2), 256 threads
__global__ void kA(const float* __restrict__ lam1, const float* __restrict__ lam2,
                   const float* __restrict__ F_src, const float* __restrict__ F_tgt,
                   const float* __restrict__ U_src, const float* __restrict__ U_tgt,
                   const int* __restrict__ A_src, const int* __restrict__ A_tgt) {
    int js = blockIdx.x, b = blockIdx.y, mat = blockIdx.z;
    int j0 = js * JW;
    const float* lam = mat ? lam2 : lam1;

    __shared__ __align__(16) float sFs[DD * NN];   // F_src[b]  [k][u]
    __shared__ __align__(16) float sFt[JW * NN];   // F_tgt[b] slice [j][v]
    __shared__ __align__(16) float sW[DD * 34];    // W[k][j] slice, stride 34
    __shared__ __align__(16) float sY[JW * 17];    // Y[j][u]

    int t = threadIdx.x;

    // stage F_src (8KB) + F_tgt slice (2KB), float4 coalesced
    {
        const float4* F4 = reinterpret_cast<const float4*>(F_src + b * DD * NN);
        float4* s4 = reinterpret_cast<float4*>(sFs);
        for (int i = t; i < DD * NN / 4; i += 256) s4[i] = F4[i];
        const float4* G4 = reinterpret_cast<const float4*>(F_tgt + b * DD * NN + j0 * NN);
        float4* g4 = reinterpret_cast<float4*>(sFt);
        if (t < JW * NN / 4) g4[t] = G4[t];
    }

    // build W slice: W[k][j] = relu(lam[k][j0+j] + lam[j0+j][k])
    // row read coalesced; transposed read is L1-resident (lam is 64KB total)
    for (int idx = t; idx < DD * JW; idx += 256) {
        int k = idx >> 5, j = idx & 31;
        float w = lam[k * DD + j0 + j] + lam[(j0 + j) * DD + k];
        sW[k * 34 + j] = fmaxf(w, 0.f);
    }
    __syncthreads();

    // Y[u][j] = sum_k sFs[k][u] * W[k][j]; thread (u = t&15, jg = t>>4) -> j = 2jg, 2jg+1
    {
        int u = t & 15, jg = t >> 4;
        float a0 = 0.f, a1 = 0.f;
#pragma unroll 8
        for (int k = 0; k < DD; ++k) {
            float fs = sFs[k * NN + u];
            float2 w = *reinterpret_cast<const float2*>(&sW[k * 34 + jg * 2]);
            a0 = fmaf(w.x, fs, a0);
            a1 = fmaf(w.y, fs, a1);
        }
        sY[(2 * jg) * 17 + u]     = a0;
        sY[(2 * jg + 1) * 17 + u] = a1;
    }
    __syncthreads();

    // partial P[u][v] = sum_j Y[u][j] * sFt[j][v]
    {
        int u = t >> 4, v = t & 15;
        float p = 0.f;
#pragma unroll
        for (int j = 0; j < JW; ++j)
            p = fmaf(sY[j * 17 + u], sFt[j * NN + v], p);
        g_Pp[((mat * JS + js) * NB + b) * 256 + t] = p;
    }

    // side outputs (one block set per b)
    if (mat == 0 && js == 0) {
        if (t < EE)
            g_mb[b * EE + t] =
                (A_src[b * EE + t] > 0 && A_tgt[b * EE + t] > 0) ? 1.f : 0.f;
        int u = t >> 4, v = t & 15;
        const float* Us = U_src + b * 256;
        const float* Ut = U_tgt + b * 256;
        float s = 0.f;
#pragma unroll
        for (int d = 0; d < NN; ++d)
            s = fmaf(Us[d * NN + u], Ut[d * NN + v], s);
        g_Mp[b * 256 + t] = s;
    }
}

// k3: out[b, i2*16+i1, j2*16+j1] = edge term + diag term
// grid (16 b, 16 i2), 256 threads: thread = (i1 = t>>4, j2 = t&15), 16 j1 each
__global__ void k3(float* __restrict__ out) {
    int b = blockIdx.x, i2 = blockIdx.y;
    __shared__ float sP1[256], sP2[256], smb[EE], sMp[16];
    int t = threadIdx.x;
    {
        float s1 = 0.f, s2 = 0.f;
#pragma unroll
        for (int js = 0; js < JS; ++js) {
            s1 += g_Pp[((0 * JS + js) * NB + b) * 256 + t];
            s2 += g_Pp[((1 * JS + js) * NB + b) * 256 + t];
        }
        sP1[t] = s1;
        sP2[t] = s2;
    }
    if (t < EE) smb[t] = g_mb[b * EE + t];
    if (t < 16) sMp[t] = g_Mp[b * 256 + i2 * 16 + t];
    __syncthreads();

    int i1 = t >> 4, j2 = t & 15;

    float me2 = 0.f;
    if (i2 < j2) me2 = smb[eidx(i2, j2)];
    float p1a = sP1[i2 * 16 + i1];   // P1[i2][i1]
    float p2b = sP2[j2 * 16 + i1];   // P2[j2][i1]

    float vals[16];
#pragma unroll
    for (int j1 = 0; j1 < 16; ++j1) {
        float val = 0.f;
        if (i2 < j2 && i1 < j1) {
            float me1 = smb[eidx(i1, j1)];
            val = me2 * me1 *
                  (p1a + sP2[i2 * 16 + j1] + p2b + sP1[j2 * 16 + j1]);
        }
        if (i2 == j2 && j1 == i1)   // diagonal of diag(Mp.flatten())
            val += sMp[i1];
        vals[j1] = val;
    }

    // row p = i2*16+i1, cols j2*16 .. j2*16+15 : 64B contiguous per thread
    float4* o = reinterpret_cast<float4*>(
        out + ((size_t)b * 65536u) + (i2 * 16 + i1) * 256 + j2 * 16);
#pragma unroll
    for (int q = 0; q < 4; ++q)
        o[q] = make_float4(vals[4 * q], vals[4 * q + 1],
                           vals[4 * q + 2], vals[4 * q + 3]);
}

extern "C" void kernel_launch(void* const* d_in, const int* in_sizes, int n_in,
                              void* d_out, int out_size) {
    const int*   A_src = (const int*)d_in[0];
    const int*   A_tgt = (const int*)d_in[1];
    const float* F_src = (const float*)d_in[2];
    const float* F_tgt = (const float*)d_in[3];
    const float* U_src = (const float*)d_in[4];
    const float* U_tgt = (const float*)d_in[5];
    const float* lam1  = (const float*)d_in[6];
    const float* lam2  = (const float*)d_in[7];
    float* out = (float*)d_out;

    kA<<<dim3(JS, NB, 2), 256>>>(lam1, lam2, F_src, F_tgt, U_src, U_tgt, A_src, A_tgt);
    k3<<<dim3(16, 16), 256>>>(out);
}

// round 6
// speedup vs baseline: 1.1204x; 1.1204x over previous
#include <cuda_runtime.h>

#define NB 16
#define DD 128
#define NN 16
#define EE 120

// Scratch (allocation-free rule: __device__ globals, zero-init at load;
// barrier counters are reset in-kernel so every graph replay sees 0)
__device__ float    g_Pp[NB][16][2][256];   // partial P[b][slice][mat][u*16+v]
__device__ float    g_Mp[NB][256];          // U_src^T U_tgt
__device__ float    g_mb[NB][EE];           // combined edge mask
__device__ unsigned g_arr[NB * 32];         // arrive counters (128B apart)
__device__ unsigned g_done[NB * 32];        // done counters

// strict-upper-triangle edge index (numpy triu_indices(16, k=1) row-major)
__device__ __forceinline__ int eidx(int i, int j) {
    return i * 15 - ((i * (i - 1)) >> 1) + (j - i - 1);
}

// grid (16 b, 16 sl), 256 threads, 2 blocks/SM guaranteed -> all 256 co-resident
__global__ void __launch_bounds__(256, 2)
fused(const float* __restrict__ lam1, const float* __restrict__ lam2,
      const float* __restrict__ F_src, const float* __restrict__ F_tgt,
      const float* __restrict__ U_src, const float* __restrict__ U_tgt,
      const int* __restrict__ A_src, const int* __restrict__ A_tgt,
      float* __restrict__ out) {
    int b  = blockIdx.x;
    int sl = blockIdx.y;           // j-slice id AND output i2
    int i2 = sl;
    int j0 = sl * 8;
    int t  = threadIdx.x;

    __shared__ __align__(16) float sFs[DD * NN];     // F_src[b]   [k][u]
    __shared__ __align__(16) float sW[2 * 8 * 130];  // W slice [m][jl][k pad 130]
    __shared__ __align__(16) float sFt[8 * NN];      // F_tgt[b] rows j0..j0+7
    __shared__ __align__(16) float sYp[8 * 2 * 16 * 8]; // Y partials [ks8][m][u][jl]
    __shared__ __align__(16) float sY[2 * 16 * 8];   // Y [m][u][jl]
    __shared__ float sP1[256], sP2[256], smb[EE], sMp[16];

    // ---- stage F_src (8KB) + F_tgt slice (512B) ----
    {
        const float4* F4 = reinterpret_cast<const float4*>(F_src + b * DD * NN);
        float4* s4 = reinterpret_cast<float4*>(sFs);
        for (int i = t; i < DD * NN / 4; i += 256) s4[i] = F4[i];
        if (t < 8 * NN / 4)
            reinterpret_cast<float4*>(sFt)[t] =
                reinterpret_cast<const float4*>(F_tgt + b * DD * NN + j0 * NN)[t];
    }

    // ---- build W[m][jl][k] = relu(lam_m[k][j0+jl] + lam_m[j0+jl][k]) ----
    // pass 1: row-major term (jl-fastest indexing)
    for (int idx = t; idx < 2048; idx += 256) {
        int m = idx >> 10, rem = idx & 1023;
        int k = rem >> 3, jl = rem & 7;
        const float* lam = m ? lam2 : lam1;
        sW[m * 1040 + jl * 130 + k] = lam[k * DD + j0 + jl];
    }
    __syncthreads();
    // pass 2: transposed term (k-fastest, fully coalesced) + relu
    for (int idx = t; idx < 2048; idx += 256) {
        int k = idx & 127, m = (idx >> 7) & 1, jl = idx >> 8;
        const float* lam = m ? lam2 : lam1;
        float w = sW[m * 1040 + jl * 130 + k] + lam[(j0 + jl) * DD + k];
        sW[m * 1040 + jl * 130 + k] = fmaxf(w, 0.f);
    }
    __syncthreads();

    // ---- Y[m][u][jl] = sum_k F_src[k][u] * W[m][k][jl] ----
    // warp = ks8 (16-wide k range); lane = (u, m). 8 accumulators/thread.
    {
        int ks8 = t >> 5;
        int u = t & 15, m = (t >> 4) & 1;
        const float* wb = sW + m * 1040;
        float y[8] = {0.f, 0.f, 0.f, 0.f, 0.f, 0.f, 0.f, 0.f};
        int kb = ks8 * 16;
#pragma unroll
        for (int kk = 0; kk < 16; ++kk) {
            int k = kb + kk;
            float fs = sFs[k * NN + u];
#pragma unroll
            for (int jl = 0; jl < 8; ++jl)
                y[jl] = fmaf(fs, wb[jl * 130 + k], y[jl]);
        }
        float* yp = sYp + ((ks8 * 2 + m) * 16 + u) * 8;
#pragma unroll
        for (int jl = 0; jl < 8; ++jl) yp[jl] = y[jl];
    }
    __syncthreads();
    // reduce Y partials over ks8
    {
        int m = t >> 7, u = (t >> 3) & 15, jl = t & 7;
        float s = 0.f;
#pragma unroll
        for (int ks8 = 0; ks8 < 8; ++ks8)
            s += sYp[((ks8 * 2 + m) * 16 + u) * 8 + jl];
        sY[(m * 16 + u) * 8 + jl] = s;
    }
    __syncthreads();

    // ---- partial P[m][u][v] = sum_jl Y[m][u][jl] * F_tgt[j0+jl][v] ----
    {
        int u = t >> 4, v = t & 15;
        float p0 = 0.f, p1 = 0.f;
#pragma unroll
        for (int jl = 0; jl < 8; ++jl) {
            float ft = sFt[jl * NN + v];
            p0 = fmaf(sY[(0 * 16 + u) * 8 + jl], ft, p0);
            p1 = fmaf(sY[(1 * 16 + u) * 8 + jl], ft, p1);
        }
        g_Pp[b][sl][0][t] = p0;   // t == u*16+v, coalesced
        g_Pp[b][sl][1][t] = p1;
    }
    // side outputs (one block per b)
    if (sl == 0) {
        if (t < EE)
            g_mb[b][t] =
                (A_src[b * EE + t] > 0 && A_tgt[b * EE + t] > 0) ? 1.f : 0.f;
        int u = t >> 4, v = t & 15;
        float s = 0.f;
#pragma unroll
        for (int d = 0; d < NN; ++d)
            s = fmaf(U_src[b * 256 + d * NN + u], U_tgt[b * 256 + d * NN + v], s);
        g_Mp[b][t] = s;
    }

    // ---- device-wide per-batch barrier (all 256 blocks wave-1 resident) ----
    __threadfence();
    __syncthreads();
    int bp = b * 32;
    if (t == 0) {
        atomicAdd(&g_arr[bp], 1u);
        // volatile-load spin (no atomic hammering on the LTS atomic ALU)
        volatile unsigned* arr = &g_arr[bp];
        while (*arr < 16u) __nanosleep(32);
        // self-reset for the next graph replay: last block through zeroes
        // both counters; every spinner has already exited its loop by then.
        unsigned d = atomicAdd(&g_done[bp], 1u);
        if (d == 15u) { g_arr[bp] = 0u; g_done[bp] = 0u; }
    }
    __syncthreads();
    __threadfence();

    // ---- sum the 16 partials (L2-resident) ----
    {
        float s1 = 0.f, s2 = 0.f;
#pragma unroll
        for (int s = 0; s < 16; ++s) {
            s1 += g_Pp[b][s][0][t];
            s2 += g_Pp[b][s][1][t];
        }
        sP1[t] = s1;
        sP2[t] = s2;
    }
    if (t < EE) smb[t] = g_mb[b][t];
    if (t < 16) sMp[t] = g_Mp[b][i2 * 16 + t];
    __syncthreads();

    // ---- output tile: rows i2*16+i1, thread = (i1 = t>>4, j2 = t&15) ----
    int i1 = t >> 4, j2 = t & 15;

    float me2 = 0.f;
    if (i2 < j2) me2 = smb[eidx(i2, j2)];
    float p1a = sP1[i2 * 16 + i1];   // P1[i2][i1]
    float p2b = sP2[j2 * 16 + i1];   // P2[j2][i1]

    float vals[16];
#pragma unroll
    for (int j1 = 0; j1 < 16; ++j1) {
        float val = 0.f;
        if (i2 < j2 && i1 < j1) {
            float me1 = smb[eidx(i1, j1)];
            val = me2 * me1 *
                  (p1a + sP2[i2 * 16 + j1] + p2b + sP1[j2 * 16 + j1]);
        }
        if (i2 == j2 && j1 == i1)   // diagonal of diag(Mp.flatten())
            val += sMp[i1];
        vals[j1] = val;
    }

    float4* o = reinterpret_cast<float4*>(
        out + ((size_t)b * 65536u) + (i2 * 16 + i1) * 256 + j2 * 16);
#pragma unroll
    for (int q = 0; q < 4; ++q)
        o[q] = make_float4(vals[4 * q], vals[4 * q + 1],
                           vals[4 * q + 2], vals[4 * q + 3]);
}

extern "C" void kernel_launch(void* const* d_in, const int* in_sizes, int n_in,
                              void* d_out, int out_size) {
    const int*   A_src = (const int*)d_in[0];
    const int*   A_tgt = (const int*)d_in[1];
    const float* F_src = (const float*)d_in[2];
    const float* F_tgt = (const float*)d_in[3];
    const float* U_src = (const float*)d_in[4];
    const float* U_tgt = (const float*)d_in[5];
    const float* lam1  = (const float*)d_in[6];
    const float* lam2  = (const float*)d_in[7];
    float* out = (float*)d_out;

    fused<<<dim3(NB, 16), 256>>>(lam1, lam2, F_src, F_tgt,
                                 U_src, U_tgt, A_src, A_tgt, out);
}

// round 13
// speedup vs baseline: 1.2626x; 1.1269x over previous
#include <cuda_runtime.h>

#define NB 16
#define DD 128
#define NN 16
#define EE 120

// Scratch (allocation-free rule: __device__ globals, zero-init at load;
// barrier counters are reset in-kernel so every graph replay sees 0)
__device__ float    g_Pp[NB][16][2][256];   // partial P[b][slice][mat][u*16+v]
__device__ float    g_Mp[NB][256];          // U_src^T U_tgt
__device__ float    g_mb[NB][EE];           // combined edge mask
__device__ unsigned g_arr[NB * 32];         // arrive counters (128B apart)
__device__ unsigned g_done[NB * 32];        // done counters

// strict-upper-triangle edge index (numpy triu_indices(16, k=1) row-major)
__device__ __forceinline__ int eidx(int i, int j) {
    return i * 15 - ((i * (i - 1)) >> 1) + (j - i - 1);
}

// grid (16 b, 16 sl), 256 threads, 2 blocks/SM -> all 256 blocks wave-1 resident
__global__ void __launch_bounds__(256, 2)
fused(const float* __restrict__ lam1, const float* __restrict__ lam2,
      const float* __restrict__ F_src, const float* __restrict__ F_tgt,
      const float* __restrict__ U_src, const float* __restrict__ U_tgt,
      const int* __restrict__ A_src, const int* __restrict__ A_tgt,
      float* __restrict__ out) {
    int b  = blockIdx.x;
    int sl = blockIdx.y;           // j-slice id AND output i2
    int i2 = sl;
    int j0 = sl * 8;
    int t  = threadIdx.x;

    __shared__ __align__(16) float sFsT[NN][132];  // F_src^T [u][k], k-contiguous
    __shared__ __align__(16) float sW[2][8][DD];   // W slice [m][jl][k], k-contiguous
    __shared__ __align__(16) float sFt[8 * NN];    // F_tgt rows j0..j0+7
    __shared__ __align__(16) float sY[2][NN][8];   // Y [m][u][jl]
    __shared__ float sP1[256], sP2[256], smb[EE], sMp[16];

    // ---- stage F_src transposed (8KB) + F_tgt slice (512B) ----
    {
        const float4* F4 = reinterpret_cast<const float4*>(F_src + b * DD * NN);
#pragma unroll
        for (int r = 0; r < 2; ++r) {
            int i = t + r * 256;            // 0..511 float4s: k = i>>2, u-quad = i&3
            float4 f = F4[i];
            int k = i >> 2, uq = (i & 3) * 4;
            sFsT[uq + 0][k] = f.x;
            sFsT[uq + 1][k] = f.y;
            sFsT[uq + 2][k] = f.z;
            sFsT[uq + 3][k] = f.w;
        }
        if (t < 8 * NN / 4)
            reinterpret_cast<float4*>(sFt)[t] =
                reinterpret_cast<const float4*>(F_tgt + b * DD * NN + j0 * NN)[t];
    }

    // ---- W single pass: W[m][jl][k] = relu(lam[k][j0+jl] + lam[j0+jl][k]) ----
    // term A coalesced (k fastest); term B strided (one 32B sector per k-row)
    {
#pragma unroll
        for (int r = 0; r < 8; ++r) {
            int idx = t + r * 256;
            int m = idx >> 10, jl = (idx >> 7) & 7, k = idx & 127;
            const float* lam = m ? lam2 : lam1;
            float w = lam[(j0 + jl) * DD + k] + lam[k * DD + j0 + jl];
            sW[m][jl][k] = fmaxf(w, 0.f);
        }
    }
    __syncthreads();

    // ---- Y[m][u][jl] = sum_k F_src[k][u] * W[m][k][jl] ----
    // warp = jl (t>>5), lane = m*16+u. All-LDS.128, 2 accumulator chains.
    {
        int jl = t >> 5, m = (t >> 4) & 1, u = t & 15;
        const float4* w4 = reinterpret_cast<const float4*>(&sW[m][jl][0]);
        const float4* f4 = reinterpret_cast<const float4*>(&sFsT[u][0]);
        float a0 = 0.f, a1 = 0.f;
#pragma unroll
        for (int q = 0; q < 32; q += 2) {
            float4 w = w4[q], f = f4[q];
            a0 = fmaf(w.x, f.x, fmaf(w.y, f.y, fmaf(w.z, f.z, fmaf(w.w, f.w, a0))));
            float4 w2 = w4[q + 1], f2 = f4[q + 1];
            a1 = fmaf(w2.x, f2.x, fmaf(w2.y, f2.y, fmaf(w2.z, f2.z, fmaf(w2.w, f2.w, a1))));
        }
        sY[m][u][jl] = a0 + a1;
    }
    __syncthreads();

    // ---- partial P[m][u][v] = sum_jl Y[m][u][jl] * F_tgt[j0+jl][v] ----
    {
        int u = t >> 4, v = t & 15;
        float p0 = 0.f, p1 = 0.f;
#pragma unroll
        for (int jl = 0; jl < 8; ++jl) {
            float ft = sFt[jl * NN + v];
            p0 = fmaf(sY[0][u][jl], ft, p0);
            p1 = fmaf(sY[1][u][jl], ft, p1);
        }
        g_Pp[b][sl][0][t] = p0;   // t == u*16+v, coalesced
        g_Pp[b][sl][1][t] = p1;
    }
    // side outputs (one block per b)
    if (sl == 0) {
        if (t < EE)
            g_mb[b][t] =
                (A_src[b * EE + t] > 0 && A_tgt[b * EE + t] > 0) ? 1.f : 0.f;
        int u = t >> 4, v = t & 15;
        float s = 0.f;
#pragma unroll
        for (int d = 0; d < NN; ++d)
            s = fmaf(U_src[b * 256 + d * NN + u], U_tgt[b * 256 + d * NN + v], s);
        g_Mp[b][t] = s;
    }

    // ---- device-wide per-batch barrier (all 256 blocks wave-1 resident) ----
    __threadfence();
    __syncthreads();
    int bp = b * 32;
    if (t == 0) {
        atomicAdd(&g_arr[bp], 1u);
        volatile unsigned* arr = &g_arr[bp];
        while (*arr < 16u) { }     // bare L2 poll (~250cy RT natural pacing)
        // self-reset for next graph replay: last block through zeroes both
        // counters; every spinner has already exited its loop by then.
        unsigned d = atomicAdd(&g_done[bp], 1u);
        if (d == 15u) { g_arr[bp] = 0u; g_done[bp] = 0u; }
    }
    __syncthreads();
    __threadfence();

    // ---- sum the 16 partials (L2-resident, 32 independent LDG) ----
    {
        float s1 = 0.f, s2 = 0.f;
#pragma unroll
        for (int s = 0; s < 16; ++s) {
            s1 += g_Pp[b][s][0][t];
            s2 += g_Pp[b][s][1][t];
        }
        sP1[t] = s1;
        sP2[t] = s2;
    }
    if (t < EE) smb[t] = g_mb[b][t];
    if (t < 16) sMp[t] = g_Mp[b][i2 * 16 + t];
    __syncthreads();

    // ---- output tile: rows i2*16+i1, thread = (i1 = t>>4, j2 = t&15) ----
    int i1 = t >> 4, j2 = t & 15;

    float me2 = 0.f;
    if (i2 < j2) me2 = smb[eidx(i2, j2)];
    float p1a = sP1[i2 * 16 + i1];   // P1[i2][i1]
    float p2b = sP2[j2 * 16 + i1];   // P2[j2][i1]

    float vals[16];
#pragma unroll
    for (int j1 = 0; j1 < 16; ++j1) {
        float val = 0.f;
        if (i2 < j2 && i1 < j1) {
            float me1 = smb[eidx(i1, j1)];
            val = me2 * me1 *
                  (p1a + sP2[i2 * 16 + j1] + p2b + sP1[j2 * 16 + j1]);
        }
        if (i2 == j2 && j1 == i1)   // diagonal of diag(Mp.flatten())
            val += sMp[i1];
        vals[j1] = val;
    }

    float4* o = reinterpret_cast<float4*>(
        out + ((size_t)b * 65536u) + (i2 * 16 + i1) * 256 + j2 * 16);
#pragma unroll
    for (int q = 0; q < 4; ++q)
        o[q] = make_float4(vals[4 * q], vals[4 * q + 1],
                           vals[4 * q + 2], vals[4 * q + 3]);
}

extern "C" void kernel_launch(void* const* d_in, const int* in_sizes, int n_in,
                              void* d_out, int out_size) {
    const int*   A_src = (const int*)d_in[0];
    const int*   A_tgt = (const int*)d_in[1];
    const float* F_src = (const float*)d_in[2];
    const float* F_tgt = (const float*)d_in[3];
    const float* U_src = (const float*)d_in[4];
    const float* U_tgt = (const float*)d_in[5];
    const float* lam1  = (const float*)d_in[6];
    const float* lam2  = (const float*)d_in[7];
    float* out = (float*)d_out;

    fused<<<dim3(NB, 16), 256>>>(lam1, lam2, F_src, F_tgt,
                                 U_src, U_tgt, A_src, A_tgt, out);
}

// round 15
// speedup vs baseline: 1.4142x; 1.1201x over previous
#include <cuda_runtime.h>

#define NB 16
#define DD 128
#define NN 16
#define EE 120

// Scratch (allocation-free rule: __device__ globals, zero-init at load;
// barrier counters are reset in-kernel so every graph replay sees 0)
__device__ float    g_Pp[NB][16][2][256];   // partial P[b][slice][mat][u*16+v]
__device__ unsigned g_arr[NB * 32];         // arrive counters (128B apart)
__device__ unsigned g_done[NB * 32];        // done counters

// strict-upper-triangle edge index (numpy triu_indices(16, k=1) row-major)
__device__ __forceinline__ int eidx(int i, int j) {
    return i * 15 - ((i * (i - 1)) >> 1) + (j - i - 1);
}

// grid (16 b, 16 sl), 256 threads, 2 blocks/SM -> all 256 blocks wave-1 resident
__global__ void __launch_bounds__(256, 2)
fused(const float* __restrict__ lam1, const float* __restrict__ lam2,
      const float* __restrict__ F_src, const float* __restrict__ F_tgt,
      const float* __restrict__ U_src, const float* __restrict__ U_tgt,
      const int* __restrict__ A_src, const int* __restrict__ A_tgt,
      float* __restrict__ out) {
    int b  = blockIdx.x;
    int sl = blockIdx.y;           // j-slice id AND output i2
    int i2 = sl;
    int j0 = sl * 8;
    int t  = threadIdx.x;

    __shared__ __align__(16) float sFsT[NN][132];   // F_src^T [u][k], k-contiguous
    __shared__ __align__(16) float sLamT[2][DD][9]; // lam[k][j0+jl], pad 9
    __shared__ __align__(16) float sW[2][8][DD];    // W slice [m][jl][k]
    __shared__ __align__(16) float sFt[8 * NN];     // F_tgt rows j0..j0+7
    __shared__ __align__(16) float sY[2][NN][8];    // Y [m][u][jl]
    __shared__ float sP1[256], sP2[256], smb[EE], sMp[16];

    // ---- phase 1: stage F_src^T, F_tgt slice, lam columns; prefetch lam rows ----
    float rA[8];
    {
        const float4* F4 = reinterpret_cast<const float4*>(F_src + b * DD * NN);
#pragma unroll
        for (int r = 0; r < 2; ++r) {
            int i = t + r * 256;            // 0..511 float4s: k = i>>2, u-quad = i&3
            float4 f = F4[i];
            int k = i >> 2, uq = (i & 3) * 4;
            sFsT[uq + 0][k] = f.x;
            sFsT[uq + 1][k] = f.y;
            sFsT[uq + 2][k] = f.z;
            sFsT[uq + 3][k] = f.w;
        }
        if (t < 8 * NN / 4)
            reinterpret_cast<float4*>(sFt)[t] =
                reinterpret_cast<const float4*>(F_tgt + b * DD * NN + j0 * NN)[t];

        // lam column slice, jl-fastest: 4 sectors per warp-LDG (8x fewer wavefronts)
#pragma unroll
        for (int r = 0; r < 8; ++r) {
            int idx = t + r * 256;
            int jl = idx & 7, k = (idx >> 3) & 127, m = idx >> 10;
            sLamT[m][k][jl] = (m ? lam2 : lam1)[k * DD + j0 + jl];
        }
        // lam row slice into registers, k-fastest: fully coalesced
#pragma unroll
        for (int r = 0; r < 8; ++r) {
            int idx = t + r * 256;
            int m = idx >> 10, jl = (idx >> 7) & 7, k = idx & 127;
            rA[r] = (m ? lam2 : lam1)[(j0 + jl) * DD + k];
        }
    }
    __syncthreads();

    // ---- W[m][jl][k] = relu(lam[j0+jl][k] + lam[k][j0+jl]) : LDS+FMA+STS only ----
    {
#pragma unroll
        for (int r = 0; r < 8; ++r) {
            int idx = t + r * 256;
            int m = idx >> 10, jl = (idx >> 7) & 7, k = idx & 127;
            sW[m][jl][k] = fmaxf(rA[r] + sLamT[m][k][jl], 0.f);
        }
    }
    __syncthreads();

    // ---- Y[m][u][jl] = sum_k F_src[k][u] * W[m][k][jl] ----
    // warp = jl (t>>5), lane = m*16+u. All-LDS.128, 2 accumulator chains.
    {
        int jl = t >> 5, m = (t >> 4) & 1, u = t & 15;
        const float4* w4 = reinterpret_cast<const float4*>(&sW[m][jl][0]);
        const float4* f4 = reinterpret_cast<const float4*>(&sFsT[u][0]);
        float a0 = 0.f, a1 = 0.f;
#pragma unroll
        for (int q = 0; q < 32; q += 2) {
            float4 w = w4[q], f = f4[q];
            a0 = fmaf(w.x, f.x, fmaf(w.y, f.y, fmaf(w.z, f.z, fmaf(w.w, f.w, a0))));
            float4 w2 = w4[q + 1], f2 = f4[q + 1];
            a1 = fmaf(w2.x, f2.x, fmaf(w2.y, f2.y, fmaf(w2.z, f2.z, fmaf(w2.w, f2.w, a1))));
        }
        sY[m][u][jl] = a0 + a1;
    }
    __syncthreads();

    // ---- partial P[m][u][v] = sum_jl Y[m][u][jl] * F_tgt[j0+jl][v] ----
    {
        int u = t >> 4, v = t & 15;
        float p0 = 0.f, p1 = 0.f;
#pragma unroll
        for (int jl = 0; jl < 8; ++jl) {
            float ft = sFt[jl * NN + v];
            p0 = fmaf(sY[0][u][jl], ft, p0);
            p1 = fmaf(sY[1][u][jl], ft, p1);
        }
        g_Pp[b][sl][0][t] = p0;   // t == u*16+v, coalesced
        g_Pp[b][sl][1][t] = p1;
    }

    // ---- per-block local side data (no global round-trip, all blocks symmetric;
    //      LDG latency absorbed by the barrier spin below) ----
    if (t < EE)
        smb[t] = (A_src[b * EE + t] > 0 && A_tgt[b * EE + t] > 0) ? 1.f : 0.f;
    if (t < 16) {
        float s = 0.f;
#pragma unroll
        for (int d = 0; d < NN; ++d)
            s = fmaf(U_src[b * 256 + d * NN + i2], U_tgt[b * 256 + d * NN + t], s);
        sMp[t] = s;   // Mp row i2: the only row this block needs
    }

    // ---- device-wide per-batch barrier (all 256 blocks wave-1 resident) ----
    __threadfence();
    __syncthreads();
    int bp = b * 32;
    if (t == 0) {
        atomicAdd(&g_arr[bp], 1u);
        volatile unsigned* arr = &g_arr[bp];
        while (*arr < 16u) { }     // bare L2 poll
        // self-reset for next graph replay: last block through zeroes both
        // counters; every spinner has already exited its loop by then.
        unsigned d = atomicAdd(&g_done[bp], 1u);
        if (d == 15u) { g_arr[bp] = 0u; g_done[bp] = 0u; }
    }
    __syncthreads();
    __threadfence();

    // ---- sum the 16 partials (L2-resident, 32 independent LDG) ----
    {
        float s1 = 0.f, s2 = 0.f;
#pragma unroll
        for (int s = 0; s < 16; ++s) {
            s1 += g_Pp[b][s][0][t];
            s2 += g_Pp[b][s][1][t];
        }
        sP1[t] = s1;
        sP2[t] = s2;
    }
    __syncthreads();

    // ---- output tile: rows i2*16+i1, thread = (i1 = t>>4, j2 = t&15) ----
    int i1 = t >> 4, j2 = t & 15;

    float me2 = 0.f;
    if (i2 < j2) me2 = smb[eidx(i2, j2)];
    float p1a = sP1[i2 * 16 + i1];   // P1[i2][i1]
    float p2b = sP2[j2 * 16 + i1];   // P2[j2][i1]

    float vals[16];
#pragma unroll
    for (int j1 = 0; j1 < 16; ++j1) {
        float val = 0.f;
        if (i2 < j2 && i1 < j1) {
            float me1 = smb[eidx(i1, j1)];
            val = me2 * me1 *
                  (p1a + sP2[i2 * 16 + j1] + p2b + sP1[j2 * 16 + j1]);
        }
        if (i2 == j2 && j1 == i1)   // diagonal of diag(Mp.flatten())
            val += sMp[i1];
        vals[j1] = val;
    }

    float4* o = reinterpret_cast<float4*>(
        out + ((size_t)b * 65536u) + (i2 * 16 + i1) * 256 + j2 * 16);
#pragma unroll
    for (int q = 0; q < 4; ++q)
        o[q] = make_float4(vals[4 * q], vals[4 * q + 1],
                           vals[4 * q + 2], vals[4 * q + 3]);
}

extern "C" void kernel_launch(void* const* d_in, const int* in_sizes, int n_in,
                              void* d_out, int out_size) {
    const int*   A_src = (const int*)d_in[0];
    const int*   A_tgt = (const int*)d_in[1];
    const float* F_src = (const float*)d_in[2];
    const float* F_tgt = (const float*)d_in[3];
    const float* U_src = (const float*)d_in[4];
    const float* U_tgt = (const float*)d_in[5];
    const float* lam1  = (const float*)d_in[6];
    const float* lam2  = (const float*)d_in[7];
    float* out = (float*)d_out;

    fused<<<dim3(NB, 16), 256>>>(lam1, lam2, F_src, F_tgt,
                                 U_src, U_tgt, A_src, A_tgt, out);
}